// round 4
// baseline (speedup 1.0000x reference)
#include <cuda_runtime.h>
#include <math.h>
#include <stdint.h>

// GAT layer, fixed shapes per reference
#define NDIM   128   // IN_DIM
#define D      64    // OUT_DIM
#define EIN    32
#define EOUT   32
#define MAXN   50000
#define MAXE   1600000
#define SCAN_BS 1024

// ---- scratch (static device allocations; no runtime alloc) ----
__device__ float g_z   [MAXN * D];     // z = h @ W_node
__device__ float g_T1  [MAXN * D];     // z @ W_tonode[:64]
__device__ float g_A1  [MAXN];         // z . W_attn[:64]
__device__ float g_A2  [MAXN];         // z . W_attn[64:128]
__device__ float g_G   [MAXN * EIN];   // (sum_e ex*ew)/den per dst
__device__ float g_P1  [MAXN * EOUT];  // h_new @ W_edge[:64]
__device__ float g_P2  [MAXN * EOUT];  // h_new @ W_edge[64:128]
__device__ int   g_deg [MAXN];
__device__ int   g_rs  [MAXN + 1];     // CSR row starts (by dst)
__device__ int   g_cur [MAXN];         // scatter cursors
__device__ int   g_bsum[64];           // scan block sums
__device__ int   g_boff[64];
// dst-sorted edge data (written by k_scat, streamed by k_agg)
__device__ float g_ews [(size_t)MAXE * EIN];  // permuted ew rows (205MB)
__device__ float g_exs [MAXE];                // exp(leaky(logit)) per sorted slot
__device__ int   g_srcs[MAXE];                // src per sorted slot

// ---------------------------------------------------------------------------
__global__ void k_init(int N) {
    int i = blockIdx.x * blockDim.x + threadIdx.x;
    if (i < N) g_deg[i] = 0;
}

// ---------------------------------------------------------------------------
// K1: z = h @ W_node   [N,128]@[128,64]
// ---------------------------------------------------------------------------
__global__ void k_z(const float* __restrict__ h, const float* __restrict__ Wn, int N) {
    __shared__ float sW[NDIM * D];        // 32 KB
    __shared__ float sH[16 * 132];
    for (int i = threadIdx.x; i < NDIM * D; i += 256) sW[i] = Wn[i];
    int nTiles = (N + 15) >> 4;
    for (int tile = blockIdx.x; tile < nTiles; tile += gridDim.x) {
        int base = tile << 4;
        __syncthreads();
        for (int i = threadIdx.x; i < 16 * NDIM; i += 256) {
            int nl = i >> 7, c = i & 127;
            int n = base + nl;
            sH[nl * 132 + c] = (n < N) ? h[(size_t)n * NDIM + c] : 0.f;
        }
        __syncthreads();
        int g4 = (threadIdx.x & 15) << 2;
        int nl = threadIdx.x >> 4;
        float4 acc = make_float4(0.f, 0.f, 0.f, 0.f);
        #pragma unroll 4
        for (int k = 0; k < NDIM; k++) {
            float hk = sH[nl * 132 + k];
            float4 w = *(const float4*)&sW[k * D + g4];
            acc.x += hk * w.x; acc.y += hk * w.y; acc.z += hk * w.z; acc.w += hk * w.w;
        }
        int n = base + nl;
        if (n < N) *(float4*)&g_z[(size_t)n * D + g4] = acc;
    }
}

// ---------------------------------------------------------------------------
// K2: T1 = z @ W_tonode[:64];  A1 = z.Wa[:64];  A2 = z.Wa[64:128]
// ---------------------------------------------------------------------------
__global__ void k_T1A(const float* __restrict__ Wt, const float* __restrict__ Wa, int N) {
    __shared__ float sW[D * D];           // 16 KB
    __shared__ float sWa[2 * D];
    __shared__ float sZ[16 * 68];
    for (int i = threadIdx.x; i < D * D; i += 256) sW[i] = Wt[i];
    if (threadIdx.x < 2 * D) sWa[threadIdx.x] = Wa[threadIdx.x];
    int nTiles = (N + 15) >> 4;
    for (int tile = blockIdx.x; tile < nTiles; tile += gridDim.x) {
        int base = tile << 4;
        __syncthreads();
        for (int i = threadIdx.x; i < 16 * D; i += 256) {
            int nl = i >> 6, c = i & 63;
            int n = base + nl;
            sZ[nl * 68 + c] = (n < N) ? g_z[(size_t)n * D + c] : 0.f;
        }
        __syncthreads();
        int g4 = (threadIdx.x & 15) << 2;
        int nl = threadIdx.x >> 4;
        int n = base + nl;
        float4 acc = make_float4(0.f, 0.f, 0.f, 0.f);
        #pragma unroll 4
        for (int k = 0; k < D; k++) {
            float zk = sZ[nl * 68 + k];
            float4 w = *(const float4*)&sW[k * D + g4];
            acc.x += zk * w.x; acc.y += zk * w.y; acc.z += zk * w.z; acc.w += zk * w.w;
        }
        if (n < N) *(float4*)&g_T1[(size_t)n * D + g4] = acc;

        float4 z4 = *(const float4*)&sZ[nl * 68 + g4];
        float p1 = z4.x * sWa[g4]     + z4.y * sWa[g4 + 1]     + z4.z * sWa[g4 + 2]     + z4.w * sWa[g4 + 3];
        float p2 = z4.x * sWa[D + g4] + z4.y * sWa[D + g4 + 1] + z4.z * sWa[D + g4 + 2] + z4.w * sWa[D + g4 + 3];
        #pragma unroll
        for (int off = 8; off >= 1; off >>= 1) {
            p1 += __shfl_down_sync(0xffffffffu, p1, off, 16);
            p2 += __shfl_down_sync(0xffffffffu, p2, off, 16);
        }
        if ((threadIdx.x & 15) == 0 && n < N) { g_A1[n] = p1; g_A2[n] = p2; }
    }
}

// ---------------------------------------------------------------------------
// CSR build: histogram -> scan (3 stages)
// ---------------------------------------------------------------------------
__global__ void k_hist(const int* __restrict__ dst, int E) {
    int e = blockIdx.x * blockDim.x + threadIdx.x;
    if (e < E) atomicAdd(&g_deg[dst[e]], 1);
}

__global__ void k_scan1(int N) {
    __shared__ int s[SCAN_BS];
    int i = blockIdx.x * SCAN_BS + threadIdx.x;
    s[threadIdx.x] = (i < N) ? g_deg[i] : 0;
    __syncthreads();
    for (int off = SCAN_BS >> 1; off > 0; off >>= 1) {
        if (threadIdx.x < off) s[threadIdx.x] += s[threadIdx.x + off];
        __syncthreads();
    }
    if (threadIdx.x == 0) g_bsum[blockIdx.x] = s[0];
}

__global__ void k_scan2(int NB, int N, int E) {
    if (threadIdx.x == 0) {
        int acc = 0;
        for (int b = 0; b < NB; b++) { g_boff[b] = acc; acc += g_bsum[b]; }
        g_rs[N] = E;
    }
}

__global__ void k_scan3(int N) {
    __shared__ int s[SCAN_BS];
    int i = blockIdx.x * SCAN_BS + threadIdx.x;
    int v = (i < N) ? g_deg[i] : 0;
    s[threadIdx.x] = v;
    __syncthreads();
    for (int off = 1; off < SCAN_BS; off <<= 1) {
        int x = (threadIdx.x >= off) ? s[threadIdx.x - off] : 0;
        __syncthreads();
        s[threadIdx.x] += x;
        __syncthreads();
    }
    if (i < N) {
        int excl = g_boff[blockIdx.x] + s[threadIdx.x] - v;
        g_rs[i]  = excl;
        g_cur[i] = excl;
    }
}

// ---------------------------------------------------------------------------
// K-SCAT: fused logit + permute. Thread per edge (coalesced ew read):
//   ex = exp(leaky(A1[s]+A2[d]+ew.Wa3));  pos = cursor(dst)
//   write srcs/exs/ews at sorted position (fire-and-forget stores)
// ---------------------------------------------------------------------------
__global__ void k_scat(const float* __restrict__ ew, const float* __restrict__ Wa,
                       const int* __restrict__ src, const int* __restrict__ dst, int E) {
    __shared__ float sWa3[EIN];
    if (threadIdx.x < EIN) sWa3[threadIdx.x] = Wa[2 * D + threadIdx.x];
    __syncthreads();
    int e = blockIdx.x * blockDim.x + threadIdx.x;
    if (e >= E) return;
    int s = src[e], d = dst[e];
    const float4* r = (const float4*)(ew + (size_t)e * EIN);
    float4 v[8];
    #pragma unroll
    for (int j = 0; j < 8; j++) v[j] = r[j];
    float a = __ldg(&g_A1[s]) + __ldg(&g_A2[d]);
    #pragma unroll
    for (int j = 0; j < 8; j++)
        a += v[j].x * sWa3[4*j] + v[j].y * sWa3[4*j+1] + v[j].z * sWa3[4*j+2] + v[j].w * sWa3[4*j+3];
    float lr = (a >= 0.f) ? a : 0.1f * a;
    float ex = __expf(lr);
    int pos = atomicAdd(&g_cur[d], 1);
    g_srcs[pos] = s;
    g_exs[pos]  = ex;
    float4* o = (float4*)(g_ews + (size_t)pos * EIN);
    #pragma unroll
    for (int j = 0; j < 8; j++) o[j] = v[j];
}

// ---------------------------------------------------------------------------
// K-AGG: warp per dst-node, streaming over its sorted segment.
// Chunked: coalesced ex/src loads (32/chunk), fully unrolled inner body,
// 3 independent loads per edge (ews sequential; T1[s] L2-resident).
// ---------------------------------------------------------------------------
__global__ void k_agg(float* __restrict__ out_h, int N) {
    int lane = threadIdx.x & 31;
    int n = (blockIdx.x * blockDim.x + threadIdx.x) >> 5;
    if (n >= N) return;
    int beg = g_rs[n], end = g_rs[n + 1];
    if (beg == end) return;              // zero in-degree: k_finish writes z
    float S0 = 0.f, S1 = 0.f, G = 0.f, den = 0.f;
    int i = beg;
    for (; i + 32 <= end; i += 32) {
        float exl = g_exs[i + lane];
        int   sl  = g_srcs[i + lane];
        #pragma unroll
        for (int j = 0; j < 32; j++) {
            float ex = __shfl_sync(0xffffffffu, exl, j);
            int   s  = __shfl_sync(0xffffffffu, sl, j);
            float t0 = __ldg(&g_T1[(size_t)s * D + lane]);
            float t1 = __ldg(&g_T1[(size_t)s * D + 32 + lane]);
            float w  = g_ews[(size_t)(i + j) * EIN + lane];
            den += ex;
            S0 += ex * t0;
            S1 += ex * t1;
            G  += ex * w;
        }
    }
    int m = end - i;
    if (m > 0) {
        float exl = (lane < m) ? g_exs[i + lane] : 0.f;
        int   sl  = (lane < m) ? g_srcs[i + lane] : 0;
        for (int j = 0; j < m; j++) {
            float ex = __shfl_sync(0xffffffffu, exl, j);
            int   s  = __shfl_sync(0xffffffffu, sl, j);
            float t0 = __ldg(&g_T1[(size_t)s * D + lane]);
            float t1 = __ldg(&g_T1[(size_t)s * D + 32 + lane]);
            float w  = g_ews[(size_t)(i + j) * EIN + lane];
            den += ex;
            S0 += ex * t0;
            S1 += ex * t1;
            G  += ex * w;
        }
    }
    float inv = 1.f / den;
    size_t off = (size_t)n * D;
    out_h[off + lane]      = S0 * inv;
    out_h[off + 32 + lane] = S1 * inv;
    g_G[(size_t)n * EIN + lane] = G * inv;
}

// ---------------------------------------------------------------------------
// K5: finish nodes: h_new = (deg>0) ? h_agg + G@Wt2 : z ; then P1/P2 = h_new@We1/2
// ---------------------------------------------------------------------------
__global__ void k_finish(const float* __restrict__ Wt2, const float* __restrict__ We,
                         float* __restrict__ out_h, int N) {
    __shared__ float sWt2[EIN * D];        // 8 KB
    __shared__ float sWe[2 * D * EOUT];    // 16 KB (We1 | We2)
    __shared__ float sG[8 * 33];
    __shared__ float sH[8 * 68];
    for (int i = threadIdx.x; i < EIN * D; i += 256) sWt2[i] = Wt2[i];
    for (int i = threadIdx.x; i < 2 * D * EOUT; i += 256) sWe[i] = We[i];
    int nTiles = (N + 7) >> 3;
    int nl = threadIdx.x >> 5;
    int c  = threadIdx.x & 31;
    for (int tile = blockIdx.x; tile < nTiles; tile += gridDim.x) {
        int base = tile << 3;
        int n = base + nl;
        bool live = (n < N);
        bool hasIn = live && (g_deg[n] > 0);
        __syncthreads();
        sG[nl * 33 + c] = hasIn ? g_G[(size_t)n * EIN + c] : 0.f;
        __syncthreads();
        if (live) {
            float gw0 = 0.f, gw1 = 0.f;
            #pragma unroll 8
            for (int k = 0; k < EIN; k++) {
                float gk = sG[nl * 33 + k];
                gw0 += gk * sWt2[k * D + c];
                gw1 += gk * sWt2[k * D + c + 32];
            }
            size_t off = (size_t)n * D;
            float h0, h1;
            if (hasIn) {
                h0 = out_h[off + c]      + gw0;
                h1 = out_h[off + c + 32] + gw1;
            } else {
                h0 = g_z[off + c];
                h1 = g_z[off + c + 32];
            }
            out_h[off + c]      = h0;
            out_h[off + c + 32] = h1;
            sH[nl * 68 + c]      = h0;
            sH[nl * 68 + c + 32] = h1;
        }
        __syncthreads();
        if (live) {
            float p1 = 0.f, p2 = 0.f;
            #pragma unroll 8
            for (int k = 0; k < D; k++) {
                float hv = sH[nl * 68 + k];
                p1 += hv * sWe[k * EOUT + c];
                p2 += hv * sWe[(D + k) * EOUT + c];
            }
            g_P1[(size_t)n * EOUT + c] = p1;
            g_P2[(size_t)n * EOUT + c] = p2;
        }
    }
}

// ---------------------------------------------------------------------------
// K6: w_new = P1[src] + P2[dst] + ew @ We3
// ---------------------------------------------------------------------------
__global__ void k_wnew(const float* __restrict__ ew, const float* __restrict__ We3,
                       const int* __restrict__ src, const int* __restrict__ dst,
                       float* __restrict__ out_w, int E) {
    __shared__ float sW[EIN * EOUT];      // 4 KB
    __shared__ float sEw[64 * 33];        // 8.4 KB
    for (int i = threadIdx.x; i < EIN * EOUT; i += 256) sW[i] = We3[i];
    int nTiles = (E + 63) >> 6;
    int el = threadIdx.x >> 2;
    int c8 = (threadIdx.x & 3) << 3;
    for (int tile = blockIdx.x; tile < nTiles; tile += gridDim.x) {
        int base = tile << 6;
        __syncthreads();
        for (int i = threadIdx.x; i < 64 * EIN; i += 256) {
            int l = i >> 5, cc = i & 31;
            sEw[l * 33 + cc] = (base + l < E) ? ew[(size_t)base * EIN + i] : 0.f;
        }
        __syncthreads();
        int e = base + el;
        if (e < E) {
            int s = src[e], d = dst[e];
            float4 a0 = *(const float4*)&g_P1[(size_t)s * EOUT + c8];
            float4 a1 = *(const float4*)&g_P1[(size_t)s * EOUT + c8 + 4];
            float4 b0 = *(const float4*)&g_P2[(size_t)d * EOUT + c8];
            float4 b1 = *(const float4*)&g_P2[(size_t)d * EOUT + c8 + 4];
            float4 acc0 = make_float4(a0.x + b0.x, a0.y + b0.y, a0.z + b0.z, a0.w + b0.w);
            float4 acc1 = make_float4(a1.x + b1.x, a1.y + b1.y, a1.z + b1.z, a1.w + b1.w);
            #pragma unroll
            for (int k = 0; k < EIN; k++) {
                float ek = sEw[el * 33 + k];
                float4 w0 = *(const float4*)&sW[k * EOUT + c8];
                float4 w1 = *(const float4*)&sW[k * EOUT + c8 + 4];
                acc0.x += ek * w0.x; acc0.y += ek * w0.y; acc0.z += ek * w0.z; acc0.w += ek * w0.w;
                acc1.x += ek * w1.x; acc1.y += ek * w1.y; acc1.z += ek * w1.z; acc1.w += ek * w1.w;
            }
            *(float4*)&out_w[(size_t)e * EOUT + c8]     = acc0;
            *(float4*)&out_w[(size_t)e * EOUT + c8 + 4] = acc1;
        }
    }
}

// ---------------------------------------------------------------------------
extern "C" void kernel_launch(void* const* d_in, const int* in_sizes, int n_in,
                              void* d_out, int out_size) {
    const float* h   = (const float*)d_in[0];   // [N,128]
    const float* ew  = (const float*)d_in[1];   // [E,32]
    const float* Wn  = (const float*)d_in[2];   // [128,64]
    const float* Wa  = (const float*)d_in[3];   // [160,1]
    const float* Wt  = (const float*)d_in[4];   // [96,64]
    const float* We  = (const float*)d_in[5];   // [160,32]
    const int*   src = (const int*)d_in[6];     // [E]
    const int*   dst = (const int*)d_in[7];     // [E]

    int N = in_sizes[0] / NDIM;
    int E = in_sizes[6];

    float* out_h = (float*)d_out;               // [N,64]
    float* out_w = out_h + (size_t)N * D;       // [E,32]

    const int PERSIST = 1184;
    int NB = (N + SCAN_BS - 1) / SCAN_BS;

    k_init   <<<(N + 255) / 256, 256>>>(N);
    k_z      <<<PERSIST, 256>>>(h, Wn, N);
    k_T1A    <<<PERSIST, 256>>>(Wt, Wa, N);
    k_hist   <<<(E + 255) / 256, 256>>>(dst, E);
    k_scan1  <<<NB, SCAN_BS>>>(N);
    k_scan2  <<<1, 32>>>(NB, N, E);
    k_scan3  <<<NB, SCAN_BS>>>(N);
    k_scat   <<<(E + 255) / 256, 256>>>(ew, Wa, src, dst, E);
    k_agg    <<<(N * 32 + 255) / 256, 256>>>(out_h, N);
    k_finish <<<PERSIST, 256>>>(Wt + D * D, We, out_h, N);
    k_wnew   <<<PERSIST, 256>>>(ew, We + 2 * D * EOUT, src, dst, out_w, E);
}

// round 5
// speedup vs baseline: 1.0831x; 1.0831x over previous
#include <cuda_runtime.h>
#include <math.h>
#include <stdint.h>

// GAT layer, fixed shapes per reference
#define NDIM   128   // IN_DIM
#define D      64    // OUT_DIM
#define EIN    32
#define EOUT   32
#define MAXN   50000
#define MAXE   1600000
#define SCAN_BS 1024

// ---- scratch (static device allocations; no runtime alloc) ----
__device__ float g_z   [MAXN * D];     // z = h @ W_node
__device__ float g_T1  [MAXN * D];     // z @ W_tonode[:64]
__device__ float g_A1  [MAXN];         // z . W_attn[:64]
__device__ float g_A2  [MAXN];         // z . W_attn[64:128]
__device__ float g_G   [MAXN * EIN];   // (sum_e ex*ew)/den per dst
__device__ float g_P1  [MAXN * EOUT];  // h_new @ W_edge[:64]
__device__ float g_P2  [MAXN * EOUT];  // h_new @ W_edge[64:128]
__device__ int   g_deg [MAXN];
__device__ int   g_rs  [MAXN + 1];     // CSR row starts (by dst)
__device__ int   g_cur [MAXN];         // scatter cursors
__device__ int   g_bsum[64];           // scan block sums
__device__ int   g_boff[64];
// dst-sorted edge metadata (12 B/edge; ew rows gathered in k_agg, NOT copied)
__device__ float g_exs [MAXE];         // exp(leaky(logit)) per sorted slot
__device__ int   g_srcs[MAXE];         // src per sorted slot
__device__ int   g_perm[MAXE];         // original edge id per sorted slot

// ---- packed f32x2 FMA helpers (FFMA2) ----
__device__ __forceinline__ uint64_t pack2(float x, float y) {
    uint64_t r; asm("mov.b64 %0, {%1, %2};" : "=l"(r) : "f"(x), "f"(y)); return r;
}
__device__ __forceinline__ void unpack2(uint64_t v, float& x, float& y) {
    asm("mov.b64 {%0, %1}, %2;" : "=f"(x), "=f"(y) : "l"(v));
}
__device__ __forceinline__ void fma2(uint64_t& acc, uint64_t a, uint64_t b) {
    asm("fma.rn.f32x2 %0, %1, %2, %0;" : "+l"(acc) : "l"(a), "l"(b));
}

// ---------------------------------------------------------------------------
__global__ void k_init(int N) {
    int i = blockIdx.x * blockDim.x + threadIdx.x;
    if (i < N) g_deg[i] = 0;
}

// ---------------------------------------------------------------------------
// K1: z = h @ W_node   [N,128]@[128,64]   (FFMA2 inner loop)
// ---------------------------------------------------------------------------
__global__ void k_z(const float* __restrict__ h, const float* __restrict__ Wn, int N) {
    __shared__ float sW[NDIM * D];        // 32 KB
    __shared__ float sH[16 * 132];
    for (int i = threadIdx.x; i < NDIM * D; i += 256) sW[i] = Wn[i];
    int nTiles = (N + 15) >> 4;
    for (int tile = blockIdx.x; tile < nTiles; tile += gridDim.x) {
        int base = tile << 4;
        __syncthreads();
        for (int i = threadIdx.x; i < 16 * NDIM; i += 256) {
            int nl = i >> 7, c = i & 127;
            int n = base + nl;
            sH[nl * 132 + c] = (n < N) ? h[(size_t)n * NDIM + c] : 0.f;
        }
        __syncthreads();
        int g4 = (threadIdx.x & 15) << 2;
        int nl = threadIdx.x >> 4;
        uint64_t acc0 = pack2(0.f, 0.f), acc1 = pack2(0.f, 0.f);
        #pragma unroll 8
        for (int k = 0; k < NDIM; k++) {
            float hk = sH[nl * 132 + k];
            uint64_t hh = pack2(hk, hk);
            const uint64_t* wp = reinterpret_cast<const uint64_t*>(&sW[k * D + g4]);
            fma2(acc0, wp[0], hh);
            fma2(acc1, wp[1], hh);
        }
        int n = base + nl;
        if (n < N) {
            float4 o;
            unpack2(acc0, o.x, o.y);
            unpack2(acc1, o.z, o.w);
            *(float4*)&g_z[(size_t)n * D + g4] = o;
        }
    }
}

// ---------------------------------------------------------------------------
// K2: T1 = z @ W_tonode[:64];  A1 = z.Wa[:64];  A2 = z.Wa[64:128]
// ---------------------------------------------------------------------------
__global__ void k_T1A(const float* __restrict__ Wt, const float* __restrict__ Wa, int N) {
    __shared__ float sW[D * D];           // 16 KB
    __shared__ float sWa[2 * D];
    __shared__ float sZ[16 * 68];
    for (int i = threadIdx.x; i < D * D; i += 256) sW[i] = Wt[i];
    if (threadIdx.x < 2 * D) sWa[threadIdx.x] = Wa[threadIdx.x];
    int nTiles = (N + 15) >> 4;
    for (int tile = blockIdx.x; tile < nTiles; tile += gridDim.x) {
        int base = tile << 4;
        __syncthreads();
        for (int i = threadIdx.x; i < 16 * D; i += 256) {
            int nl = i >> 6, c = i & 63;
            int n = base + nl;
            sZ[nl * 68 + c] = (n < N) ? g_z[(size_t)n * D + c] : 0.f;
        }
        __syncthreads();
        int g4 = (threadIdx.x & 15) << 2;
        int nl = threadIdx.x >> 4;
        int n = base + nl;
        uint64_t acc0 = pack2(0.f, 0.f), acc1 = pack2(0.f, 0.f);
        #pragma unroll 8
        for (int k = 0; k < D; k++) {
            float zk = sZ[nl * 68 + k];
            uint64_t zz = pack2(zk, zk);
            const uint64_t* wp = reinterpret_cast<const uint64_t*>(&sW[k * D + g4]);
            fma2(acc0, wp[0], zz);
            fma2(acc1, wp[1], zz);
        }
        if (n < N) {
            float4 o;
            unpack2(acc0, o.x, o.y);
            unpack2(acc1, o.z, o.w);
            *(float4*)&g_T1[(size_t)n * D + g4] = o;
        }

        float4 z4 = *(const float4*)&sZ[nl * 68 + g4];
        float p1 = z4.x * sWa[g4]     + z4.y * sWa[g4 + 1]     + z4.z * sWa[g4 + 2]     + z4.w * sWa[g4 + 3];
        float p2 = z4.x * sWa[D + g4] + z4.y * sWa[D + g4 + 1] + z4.z * sWa[D + g4 + 2] + z4.w * sWa[D + g4 + 3];
        #pragma unroll
        for (int off = 8; off >= 1; off >>= 1) {
            p1 += __shfl_down_sync(0xffffffffu, p1, off, 16);
            p2 += __shfl_down_sync(0xffffffffu, p2, off, 16);
        }
        if ((threadIdx.x & 15) == 0 && n < N) { g_A1[n] = p1; g_A2[n] = p2; }
    }
}

// ---------------------------------------------------------------------------
// CSR build: histogram -> scan (3 stages)
// ---------------------------------------------------------------------------
__global__ void k_hist(const int* __restrict__ dst, int E) {
    int e = blockIdx.x * blockDim.x + threadIdx.x;
    if (e < E) atomicAdd(&g_deg[dst[e]], 1);
}

__global__ void k_scan1(int N) {
    __shared__ int s[SCAN_BS];
    int i = blockIdx.x * SCAN_BS + threadIdx.x;
    s[threadIdx.x] = (i < N) ? g_deg[i] : 0;
    __syncthreads();
    for (int off = SCAN_BS >> 1; off > 0; off >>= 1) {
        if (threadIdx.x < off) s[threadIdx.x] += s[threadIdx.x + off];
        __syncthreads();
    }
    if (threadIdx.x == 0) g_bsum[blockIdx.x] = s[0];
}

__global__ void k_scan2(int NB, int N, int E) {
    if (threadIdx.x == 0) {
        int acc = 0;
        for (int b = 0; b < NB; b++) { g_boff[b] = acc; acc += g_bsum[b]; }
        g_rs[N] = E;
    }
}

__global__ void k_scan3(int N) {
    __shared__ int s[SCAN_BS];
    int i = blockIdx.x * SCAN_BS + threadIdx.x;
    int v = (i < N) ? g_deg[i] : 0;
    s[threadIdx.x] = v;
    __syncthreads();
    for (int off = 1; off < SCAN_BS; off <<= 1) {
        int x = (threadIdx.x >= off) ? s[threadIdx.x - off] : 0;
        __syncthreads();
        s[threadIdx.x] += x;
        __syncthreads();
    }
    if (i < N) {
        int excl = g_boff[blockIdx.x] + s[threadIdx.x] - v;
        g_rs[i]  = excl;
        g_cur[i] = excl;
    }
}

// ---------------------------------------------------------------------------
// K-SCAT: fused logit + permutation metadata. Thread per edge (coalesced ew):
//   ex = exp(leaky(A1[s]+A2[d]+ew.Wa3)); pos = cursor(dst)
//   write srcs/exs/perm at sorted position (12 B/edge — no row copy)
// ---------------------------------------------------------------------------
__global__ void k_scat(const float* __restrict__ ew, const float* __restrict__ Wa,
                       const int* __restrict__ src, const int* __restrict__ dst, int E) {
    __shared__ float sWa3[EIN];
    if (threadIdx.x < EIN) sWa3[threadIdx.x] = Wa[2 * D + threadIdx.x];
    __syncthreads();
    int e = blockIdx.x * blockDim.x + threadIdx.x;
    if (e >= E) return;
    int s = src[e], d = dst[e];
    const float4* r = (const float4*)(ew + (size_t)e * EIN);
    float a = __ldg(&g_A1[s]) + __ldg(&g_A2[d]);
    #pragma unroll
    for (int j = 0; j < 8; j++) {
        float4 v = r[j];
        a += v.x * sWa3[4*j] + v.y * sWa3[4*j+1] + v.z * sWa3[4*j+2] + v.w * sWa3[4*j+3];
    }
    float lr = (a >= 0.f) ? a : 0.1f * a;
    float ex = __expf(lr);
    int pos = atomicAdd(&g_cur[d], 1);
    g_srcs[pos] = s;
    g_exs[pos]  = ex;
    g_perm[pos] = e;
}

// ---------------------------------------------------------------------------
// K-AGG: warp per dst-node. Coalesced chunk loads of (exs, srcs, perm),
// then guarded fully-unrolled body: per edge 3 independent line loads
// (ew row via perm — full 128B line per warp; T1[s] two L2-resident lines).
// No per-edge reduce, no expf: pure streaming accumulate.
// ---------------------------------------------------------------------------
__global__ void k_agg(const float* __restrict__ ew, float* __restrict__ out_h, int N) {
    int lane = threadIdx.x & 31;
    int n = (blockIdx.x * blockDim.x + threadIdx.x) >> 5;
    if (n >= N) return;
    int beg = g_rs[n], end = g_rs[n + 1];
    if (beg == end) return;              // zero in-degree: k_finish writes z
    float S0 = 0.f, S1 = 0.f, G = 0.f, den = 0.f;
    for (int i = beg; i < end; i += 32) {
        int m = end - i; if (m > 32) m = 32;
        float exl = 0.f; int sl = 0, el = 0;
        if (lane < m) {
            exl = g_exs[i + lane];
            sl  = g_srcs[i + lane];
            el  = g_perm[i + lane];
        }
        #pragma unroll
        for (int j = 0; j < 32; j++) {
            float ex = __shfl_sync(0xffffffffu, exl, j);
            int   s  = __shfl_sync(0xffffffffu, sl, j);
            int   e  = __shfl_sync(0xffffffffu, el, j);
            if (j < m) {
                float t0 = __ldg(&g_T1[(size_t)s * D + lane]);
                float t1 = __ldg(&g_T1[(size_t)s * D + 32 + lane]);
                float w  = __ldg(&ew[(size_t)e * EIN + lane]);
                den += ex;
                S0 += ex * t0;
                S1 += ex * t1;
                G  += ex * w;
            }
        }
    }
    float inv = 1.f / den;
    size_t off = (size_t)n * D;
    out_h[off + lane]      = S0 * inv;
    out_h[off + 32 + lane] = S1 * inv;
    g_G[(size_t)n * EIN + lane] = G * inv;
}

// ---------------------------------------------------------------------------
// K5: finish nodes: h_new = (deg>0) ? h_agg + G@Wt2 : z ; then P1/P2 = h_new@We1/2
// ---------------------------------------------------------------------------
__global__ void k_finish(const float* __restrict__ Wt2, const float* __restrict__ We,
                         float* __restrict__ out_h, int N) {
    __shared__ float sWt2[EIN * D];        // 8 KB
    __shared__ float sWe[2 * D * EOUT];    // 16 KB (We1 | We2)
    __shared__ float sG[8 * 33];
    __shared__ float sH[8 * 68];
    for (int i = threadIdx.x; i < EIN * D; i += 256) sWt2[i] = Wt2[i];
    for (int i = threadIdx.x; i < 2 * D * EOUT; i += 256) sWe[i] = We[i];
    int nTiles = (N + 7) >> 3;
    int nl = threadIdx.x >> 5;
    int c  = threadIdx.x & 31;
    for (int tile = blockIdx.x; tile < nTiles; tile += gridDim.x) {
        int base = tile << 3;
        int n = base + nl;
        bool live = (n < N);
        bool hasIn = live && (g_deg[n] > 0);
        __syncthreads();
        sG[nl * 33 + c] = hasIn ? g_G[(size_t)n * EIN + c] : 0.f;
        __syncthreads();
        if (live) {
            float gw0 = 0.f, gw1 = 0.f;
            #pragma unroll 8
            for (int k = 0; k < EIN; k++) {
                float gk = sG[nl * 33 + k];
                gw0 += gk * sWt2[k * D + c];
                gw1 += gk * sWt2[k * D + c + 32];
            }
            size_t off = (size_t)n * D;
            float h0, h1;
            if (hasIn) {
                h0 = out_h[off + c]      + gw0;
                h1 = out_h[off + c + 32] + gw1;
            } else {
                h0 = g_z[off + c];
                h1 = g_z[off + c + 32];
            }
            out_h[off + c]      = h0;
            out_h[off + c + 32] = h1;
            sH[nl * 68 + c]      = h0;
            sH[nl * 68 + c + 32] = h1;
        }
        __syncthreads();
        if (live) {
            float p1 = 0.f, p2 = 0.f;
            #pragma unroll 8
            for (int k = 0; k < D; k++) {
                float hv = sH[nl * 68 + k];
                p1 += hv * sWe[k * EOUT + c];
                p2 += hv * sWe[(D + k) * EOUT + c];
            }
            g_P1[(size_t)n * EOUT + c] = p1;
            g_P2[(size_t)n * EOUT + c] = p2;
        }
    }
}

// ---------------------------------------------------------------------------
// K6: w_new = P1[src] + P2[dst] + ew @ We3   (FFMA2 inner loop)
// ---------------------------------------------------------------------------
__global__ void k_wnew(const float* __restrict__ ew, const float* __restrict__ We3,
                       const int* __restrict__ src, const int* __restrict__ dst,
                       float* __restrict__ out_w, int E) {
    __shared__ float sW[EIN * EOUT];      // 4 KB
    __shared__ float sEw[64 * 33];        // 8.4 KB
    for (int i = threadIdx.x; i < EIN * EOUT; i += 256) sW[i] = We3[i];
    int nTiles = (E + 63) >> 6;
    int el = threadIdx.x >> 2;
    int c8 = (threadIdx.x & 3) << 3;
    for (int tile = blockIdx.x; tile < nTiles; tile += gridDim.x) {
        int base = tile << 6;
        __syncthreads();
        for (int i = threadIdx.x; i < 64 * EIN; i += 256) {
            int l = i >> 5, cc = i & 31;
            sEw[l * 33 + cc] = (base + l < E) ? ew[(size_t)base * EIN + i] : 0.f;
        }
        __syncthreads();
        int e = base + el;
        if (e < E) {
            int s = src[e], d = dst[e];
            float4 a0 = *(const float4*)&g_P1[(size_t)s * EOUT + c8];
            float4 a1 = *(const float4*)&g_P1[(size_t)s * EOUT + c8 + 4];
            float4 b0 = *(const float4*)&g_P2[(size_t)d * EOUT + c8];
            float4 b1 = *(const float4*)&g_P2[(size_t)d * EOUT + c8 + 4];
            uint64_t acc0 = pack2(a0.x + b0.x, a0.y + b0.y);
            uint64_t acc1 = pack2(a0.z + b0.z, a0.w + b0.w);
            uint64_t acc2 = pack2(a1.x + b1.x, a1.y + b1.y);
            uint64_t acc3 = pack2(a1.z + b1.z, a1.w + b1.w);
            #pragma unroll
            for (int k = 0; k < EIN; k++) {
                float ek = sEw[el * 33 + k];
                uint64_t ekk = pack2(ek, ek);
                const uint64_t* wp = reinterpret_cast<const uint64_t*>(&sW[k * EOUT + c8]);
                fma2(acc0, wp[0], ekk);
                fma2(acc1, wp[1], ekk);
                fma2(acc2, wp[2], ekk);
                fma2(acc3, wp[3], ekk);
            }
            float4 o0, o1;
            unpack2(acc0, o0.x, o0.y);
            unpack2(acc1, o0.z, o0.w);
            unpack2(acc2, o1.x, o1.y);
            unpack2(acc3, o1.z, o1.w);
            *(float4*)&out_w[(size_t)e * EOUT + c8]     = o0;
            *(float4*)&out_w[(size_t)e * EOUT + c8 + 4] = o1;
        }
    }
}

// ---------------------------------------------------------------------------
extern "C" void kernel_launch(void* const* d_in, const int* in_sizes, int n_in,
                              void* d_out, int out_size) {
    const float* h   = (const float*)d_in[0];   // [N,128]
    const float* ew  = (const float*)d_in[1];   // [E,32]
    const float* Wn  = (const float*)d_in[2];   // [128,64]
    const float* Wa  = (const float*)d_in[3];   // [160,1]
    const float* Wt  = (const float*)d_in[4];   // [96,64]
    const float* We  = (const float*)d_in[5];   // [160,32]
    const int*   src = (const int*)d_in[6];     // [E]
    const int*   dst = (const int*)d_in[7];     // [E]

    int N = in_sizes[0] / NDIM;
    int E = in_sizes[6];

    float* out_h = (float*)d_out;               // [N,64]
    float* out_w = out_h + (size_t)N * D;       // [E,32]

    const int PERSIST = 1184;
    int NB = (N + SCAN_BS - 1) / SCAN_BS;

    k_init   <<<(N + 255) / 256, 256>>>(N);
    k_z      <<<PERSIST, 256>>>(h, Wn, N);
    k_T1A    <<<PERSIST, 256>>>(Wt, Wa, N);
    k_hist   <<<(E + 255) / 256, 256>>>(dst, E);
    k_scan1  <<<NB, SCAN_BS>>>(N);
    k_scan2  <<<1, 32>>>(NB, N, E);
    k_scan3  <<<NB, SCAN_BS>>>(N);
    k_scat   <<<(E + 255) / 256, 256>>>(ew, Wa, src, dst, E);
    k_agg    <<<(N * 32 + 255) / 256, 256>>>(ew, out_h, N);
    k_finish <<<PERSIST, 256>>>(Wt + D * D, We, out_h, N);
    k_wnew   <<<PERSIST, 256>>>(ew, We + 2 * D * EOUT, src, dst, out_w, E);
}